// round 11
// baseline (speedup 1.0000x reference)
#include <cuda_runtime.h>
#include <cuda_bf16.h>
#include <math.h>

#define SCALE_F 0.125f
#define EPS_F 1e-5f

// ---------------- scratch (device globals) ----------------
__device__ unsigned g_wu[2048 * 512];       // w packed bf16x2 [row][k/2]
__device__ unsigned g_ru[1024 * 512];       // r packed bf16x2
__device__ unsigned g_WqkvT[3072 * 512];    // W_qkv^T bf16x2 [n][k/2]
__device__ unsigned g_WrfwT[1024 * 512];    // W_r_fw^T bf16x2
__device__ unsigned g_WrbwT[1024 * 512];    // W_r_bw^T bf16x2
__device__ unsigned g_WoT[1024 * 512];      // W_o^T bf16x2
__device__ unsigned g_q1u[32 * 1024 * 32];  // q + r_w_bias, bf16x2 [z][i][32]
__device__ unsigned g_q2u[32 * 1024 * 32];  // q + r_r_bias, bf16x2
__device__ unsigned g_kku[32 * 1024 * 32];  // k heads, bf16x2
__device__ float    g_vv[32 * 1024 * 64];   // v heads fp32 [z][i][64]
__device__ unsigned g_vvt[32 * 64 * 512];   // v transposed bf16x2 [z][d][j/2]
__device__ unsigned g_rku[2048 * 512];      // r_k bf16x2 [jr][512] (row 2047 zeroed)
__device__ __nv_bfloat16 g_bdh[67108864];   // BD bf16, row-parity-shifted band
__device__ unsigned g_vecu[2048 * 512];     // attn vec bf16x2 [(i*2+b)][(n*64+d)/2]
__device__ float    g_x[2048 * 1024];       // vec @ W_o fp32

// ---------------- helpers ----------------
__device__ __forceinline__ void cp16(void* s, const void* g) {
    unsigned a = (unsigned)__cvta_generic_to_shared(s);
    asm volatile("cp.async.cg.shared.global [%0], [%1], 16;\n" ::"r"(a), "l"(g));
}
__device__ __forceinline__ unsigned packbf(float lo, float hi) {
    unsigned u;
    asm("cvt.rn.bf16x2.f32 %0, %1, %2;" : "=r"(u) : "f"(hi), "f"(lo));
    return u;
}
// bf16x2 rows of 32 u32 (=64 bf16), XOR swizzle
__device__ __forceinline__ int adru(int r, int c) {
    return r * 32 + (((c >> 2) ^ (r & 7)) << 2) + (c & 3);
}
#define MMA_BF16(c, a, b)                                                          \
    asm volatile(                                                                  \
        "mma.sync.aligned.m16n8k16.row.col.f32.bf16.bf16.f32 "                     \
        "{%0,%1,%2,%3},{%4,%5,%6,%7},{%8,%9},{%0,%1,%2,%3};"                       \
        : "+f"(c[0]), "+f"(c[1]), "+f"(c[2]), "+f"(c[3])                           \
        : "r"(a[0]), "r"(a[1]), "r"(a[2]), "r"(a[3]), "r"(b[0]), "r"(b[1]))

// ---------------- conversion kernels ----------------
__global__ __launch_bounds__(256) void pack_k(const float* __restrict__ in,
                                              unsigned* __restrict__ out, int n2) {
    int i = blockIdx.x * 256 + threadIdx.x;
    if (i < n2) {
        float2 v = ((const float2*)in)[i];
        out[i] = packbf(v.x, v.y);
    }
}
// fp32 [K][N] -> u32 [N][K/2] (transpose + pack). K=1024 (row stride 512 u32).
__device__ __forceinline__ void packT_body(const float* in, unsigned* out, int N) {
    __shared__ float ts[64][65];
    int t = threadIdx.x, n0 = blockIdx.x * 64, k0 = blockIdx.y * 64;
#pragma unroll
    for (int e = 0; e < 16; e++) {
        int idx = e * 256 + t, kk = idx >> 6, nn = idx & 63;
        ts[kk][nn] = in[(long long)(k0 + kk) * N + n0 + nn];
    }
    __syncthreads();
#pragma unroll
    for (int e = 0; e < 8; e++) {
        int idx = e * 256 + t, nn = idx >> 5, kp = idx & 31;
        out[(long long)(n0 + nn) * 512 + (k0 >> 1) + kp] =
            packbf(ts[2 * kp][nn], ts[2 * kp + 1][nn]);
    }
}
__global__ __launch_bounds__(256) void packT_k(const float* __restrict__ in,
                                               unsigned* __restrict__ out, int N) {
    packT_body(in, out, N);
}
// merged transpose-pack of three 1024x1024 weights (z selects)
__global__ __launch_bounds__(256) void packT3_k(
    const float* __restrict__ i0, unsigned* __restrict__ o0,
    const float* __restrict__ i1, unsigned* __restrict__ o1,
    const float* __restrict__ i2, unsigned* __restrict__ o2) {
    const float* in = (blockIdx.z == 0) ? i0 : (blockIdx.z == 1) ? i1 : i2;
    unsigned* out = (blockIdx.z == 0) ? o0 : (blockIdx.z == 1) ? o1 : o2;
    packT_body(in, out, 1024);
}
__global__ void zero_u(unsigned* p) { p[blockIdx.x * 256 + threadIdx.x] = 0u; }

// ---------------- bf16 GEMM 128x128, both operands u32 [rows][k/2] ----------------
// EPI 0: plain fp32 store to f4 (ldc=1024). EPI 2: QKV head scatter. EPI 3: rk.
template <int EPI>
__global__ __launch_bounds__(256, 2) void bgemm_k(
    const unsigned* __restrict__ A, const unsigned* __restrict__ B,
    int KU, int ldau, int ldbu,
    const unsigned* __restrict__ B2,
    const float* __restrict__ bias1, const float* __restrict__ bias2,
    unsigned* __restrict__ u1, unsigned* __restrict__ u2, unsigned* __restrict__ u3,
    float* __restrict__ f4) {
    extern __shared__ unsigned su[];
    int t = threadIdx.x, lane = t & 31, lq = lane & 3, lr = lane >> 2;
    int row0 = blockIdx.y * 128;
    int col0 = (EPI == 3) ? (blockIdx.x & 7) * 128 : blockIdx.x * 128;
    bool bw = (EPI == 3) && (blockIdx.x >= 8);
    if (bw) B = B2;
    int warp = t >> 5, wm = warp >> 1, wn = warp & 1;

    float acc[2][8][4] = {};

    auto load_tile = [&](int kt, int st) {
        unsigned* sA = su + st * 8192;
        unsigned* sB = sA + 4096;
        int k0 = kt * 32;
#pragma unroll
        for (int e = 0; e < 4; e++) {
            int c = e * 256 + t, r = c >> 3, c4 = c & 7;
            cp16(sA + r * 32 + ((c4 ^ (r & 7)) << 2),
                 A + (long long)(row0 + r) * ldau + k0 + c4 * 4);
            cp16(sB + r * 32 + ((c4 ^ (r & 7)) << 2),
                 B + (long long)(col0 + r) * ldbu + k0 + c4 * 4);
        }
        asm volatile("cp.async.commit_group;\n");
    };

    load_tile(0, 0);
    int KT = KU >> 5;
    for (int kt = 0; kt < KT; kt++) {
        int st = kt & 1;
        if (kt + 1 < KT) {
            load_tile(kt + 1, st ^ 1);
            asm volatile("cp.async.wait_group 1;\n");
        } else {
            asm volatile("cp.async.wait_group 0;\n");
        }
        __syncthreads();
        unsigned* sA = su + st * 8192;
        unsigned* sB = sA + 4096;
#pragma unroll
        for (int s = 0; s < 4; s++) {
            unsigned af[2][4], bf[8][2];
#pragma unroll
            for (int mt = 0; mt < 2; mt++) {
                int r = wm * 32 + mt * 16 + lr;
                af[mt][0] = sA[adru(r, s * 8 + lq)];
                af[mt][1] = sA[adru(r + 8, s * 8 + lq)];
                af[mt][2] = sA[adru(r, s * 8 + 4 + lq)];
                af[mt][3] = sA[adru(r + 8, s * 8 + 4 + lq)];
            }
#pragma unroll
            for (int nt = 0; nt < 8; nt++) {
                int nn = wn * 64 + nt * 8 + lr;
                bf[nt][0] = sB[adru(nn, s * 8 + lq)];
                bf[nt][1] = sB[adru(nn, s * 8 + 4 + lq)];
            }
#pragma unroll
            for (int mt = 0; mt < 2; mt++)
#pragma unroll
                for (int nt = 0; nt < 8; nt++) MMA_BF16(acc[mt][nt], af[mt], bf[nt]);
        }
        __syncthreads();
    }

#pragma unroll
    for (int mt = 0; mt < 2; mt++)
#pragma unroll
        for (int nt = 0; nt < 8; nt++) {
            int r0 = row0 + wm * 32 + mt * 16 + lr;
            int cb = col0 + wn * 64 + nt * 8 + 2 * lq;
#pragma unroll
            for (int pe = 0; pe < 2; pe++) {
                int rr = r0 + pe * 8;
                float v0 = acc[mt][nt][pe * 2], v1 = acc[mt][nt][pe * 2 + 1];
                if (EPI == 0) {
                    f4[(long long)rr * 1024 + cb] = v0;
                    f4[(long long)rr * 1024 + cb + 1] = v1;
                } else if (EPI == 3) {
                    if (bw) {
                        if (rr == 1023) continue;  // fw owns rk row 1023
                        u2[(long long)rr * (-512) + (cb >> 1)] = packbf(v0, v1);
                    } else {
                        u1[(long long)rr * 512 + (cb >> 1)] = packbf(v0, v1);
                    }
                } else {  // EPI == 2: QKV scatter
                    int i = rr >> 1, bb = rr & 1;
                    int sec = cb >> 10, c1 = cb & 1023, n = c1 >> 6, d = c1 & 63;
                    int z = bb * 16 + n;
                    if (sec == 0) {
                        long long idx = ((long long)z << 15) + (i << 5) + (d >> 1);
                        u1[idx] = packbf(v0 + bias1[c1], v1 + bias1[c1 + 1]);
                        u2[idx] = packbf(v0 + bias2[c1], v1 + bias2[c1 + 1]);
                    } else if (sec == 1) {
                        u3[((long long)z << 15) + (i << 5) + (d >> 1)] = packbf(v0, v1);
                    } else {
                        long long idx = ((long long)z << 16) + (i << 6) + d;
                        f4[idx] = v0; f4[idx + 1] = v1;
                    }
                }
            }
        }
}

// ---------------- V transpose: vv[z][j][d] fp32 -> vvt[z][d][j/2] bf16x2 ----------------
__global__ __launch_bounds__(256) void vt_k(const float* __restrict__ vv,
                                            unsigned* __restrict__ vvt) {
    __shared__ float ts[128][65];
    int t = threadIdx.x, z = blockIdx.y, j0 = blockIdx.x * 128;
    const float* Vz = vv + ((long long)z << 16);
#pragma unroll
    for (int e = 0; e < 8; e++) {
        int idx = e * 256 + t, r = idx >> 4, c4 = idx & 15;
        float4 v = *(const float4*)(Vz + (long long)(j0 + r) * 64 + c4 * 4);
        ts[r][c4 * 4] = v.x; ts[r][c4 * 4 + 1] = v.y;
        ts[r][c4 * 4 + 2] = v.z; ts[r][c4 * 4 + 3] = v.w;
    }
    __syncthreads();
#pragma unroll
    for (int e = 0; e < 16; e++) {
        int idx = e * 256 + t, d = idx >> 6, jp = idx & 63;
        vvt[((long long)z << 15) + (d << 9) + (j0 >> 1) + jp] =
            packbf(ts[jp * 2][d], ts[jp * 2 + 1][d]);
    }
}

// ---------------- bf16 BD band GEMM -> bf16 band, row-parity shift ----------------
// Row i stored at column jr + ((i+1)&1) so flash reads are u32-aligned pairs.
__global__ __launch_bounds__(256, 2) void bd_k(
    const unsigned* __restrict__ q2, const unsigned* __restrict__ rk,
    __nv_bfloat16* __restrict__ bdh) {
    __shared__ unsigned su[2 * 4096];
    unsigned* sA = su;
    unsigned* sB = su + 4096;
    int t = threadIdx.x, lane = t & 31, lq = lane & 3, lr = lane >> 2;
    int z = blockIdx.z;
    const unsigned* Az = q2 + ((long long)z << 15);
    const unsigned* Bz = rk + (long long)(z & 15) * 32;
    __nv_bfloat16* C16 = bdh + ((long long)z << 21);
    int row0 = blockIdx.y * 128;
    int col0 = 896 - row0 + blockIdx.x * 128;
    int warp = t >> 5, wm = warp >> 1, wn = warp & 1;

#pragma unroll
    for (int e = 0; e < 4; e++) {
        int c = e * 256 + t, r = c >> 3, c4 = c & 7;
        cp16(sA + r * 32 + ((c4 ^ (r & 7)) << 2), Az + (long long)(row0 + r) * 32 + c4 * 4);
        cp16(sB + r * 32 + ((c4 ^ (r & 7)) << 2), Bz + (long long)(col0 + r) * 512 + c4 * 4);
    }
    asm volatile("cp.async.commit_group;\ncp.async.wait_group 0;\n");
    __syncthreads();

    float acc[2][8][4] = {};
#pragma unroll
    for (int s = 0; s < 4; s++) {
        unsigned af[2][4], bf[8][2];
#pragma unroll
        for (int mt = 0; mt < 2; mt++) {
            int r = wm * 32 + mt * 16 + lr;
            af[mt][0] = sA[adru(r, s * 8 + lq)];
            af[mt][1] = sA[adru(r + 8, s * 8 + lq)];
            af[mt][2] = sA[adru(r, s * 8 + 4 + lq)];
            af[mt][3] = sA[adru(r + 8, s * 8 + 4 + lq)];
        }
#pragma unroll
        for (int nt = 0; nt < 8; nt++) {
            int nn = wn * 64 + nt * 8 + lr;
            bf[nt][0] = sB[adru(nn, s * 8 + lq)];
            bf[nt][1] = sB[adru(nn, s * 8 + 4 + lq)];
        }
#pragma unroll
        for (int mt = 0; mt < 2; mt++)
#pragma unroll
            for (int nt = 0; nt < 8; nt++) MMA_BF16(acc[mt][nt], af[mt], bf[nt]);
    }

#pragma unroll
    for (int mt = 0; mt < 2; mt++)
#pragma unroll
        for (int nt = 0; nt < 8; nt++) {
            int r0 = row0 + wm * 32 + mt * 16 + lr;
            int cb = col0 + wn * 64 + nt * 8 + 2 * lq;
#pragma unroll
            for (int pe = 0; pe < 2; pe++) {
                int rr = r0 + pe * 8;
                int srr = (rr + 1) & 1;
                long long p = ((long long)rr << 11) + cb + srr;
                C16[p] = __float2bfloat16(acc[mt][nt][pe * 2]);
                C16[p + 1] = __float2bfloat16(acc[mt][nt][pe * 2 + 1]);
            }
        }
}

// ---------------- flash (bf16): S = Q1·K^T + BD_band, mask, online softmax, P·V ----------------
__global__ __launch_bounds__(256, 2) void flash_k(
    const unsigned* __restrict__ q1, const unsigned* __restrict__ kk,
    const unsigned* __restrict__ vvt, const __nv_bfloat16* __restrict__ bdh,
    const unsigned char* __restrict__ mask, unsigned* __restrict__ vecu) {
    extern __shared__ unsigned fsu[];
    unsigned* sQ = fsu;                   // 128 x 32 u32
    unsigned* sP = sQ + 4096;             // 128 x 32 u32
    unsigned* sK = sP + 4096;             // 3 x 64 x 32 u32
    unsigned* sVt = sK + 3 * 2048;        // 3 x 64 x 32 u32 (rows = d)
    float* sMask = (float*)(sVt + 3 * 2048);  // 1024 flags

    int t = threadIdx.x, lane = t & 31, warp = t >> 5;
    int lq = lane & 3, lr = lane >> 2;
    int i0 = blockIdx.x * 128, z = blockIdx.y, b = z >> 4, nh = z & 15;
    const unsigned* Qz = q1 + ((long long)z << 15);
    const unsigned* Kz = kk + ((long long)z << 15);
    const unsigned* Vtz = vvt + ((long long)z << 15);
    const unsigned* bdz32 = (const unsigned*)(bdh + ((long long)z << 21));

    for (int e = t; e < 1024; e += 256) sMask[e] = mask[e * 2 + b] ? 1.0f : 0.0f;

#pragma unroll
    for (int e = 0; e < 4; e++) {
        int c = e * 256 + t, r = c >> 3, c4 = c & 7;
        cp16(sQ + r * 32 + ((c4 ^ (r & 7)) << 2), Qz + (long long)(i0 + r) * 32 + c4 * 4);
    }
    auto loadKV = [&](int jt, int bufi) {
        unsigned* dK = sK + bufi * 2048;
        unsigned* dV = sVt + bufi * 2048;
        int j0 = jt * 64;
#pragma unroll
        for (int e = 0; e < 2; e++) {
            int c = e * 256 + t, r = c >> 3, c4 = c & 7;
            cp16(dK + r * 32 + ((c4 ^ (r & 7)) << 2), Kz + (long long)(j0 + r) * 32 + c4 * 4);
            cp16(dV + r * 32 + ((c4 ^ (r & 7)) << 2),
                 Vtz + ((long long)r << 9) + (j0 >> 1) + c4 * 4);
        }
        asm volatile("cp.async.commit_group;\n");
    };
    loadKV(0, 0);
    loadKV(1, 1);

    float mA = -3.4e38f, mB = -3.4e38f, lA = 0.f, lB = 0.f;
    float O[8][4] = {};
    int rb = warp * 16 + lr;
    int rowA = i0 + rb;
    int sft = (rowA + 1) & 1;  // same parity for rowA and rowA+8
    // u32 base indices for BD pair loads (aligned thanks to the parity shift)
    long long bd0 = (((long long)rowA << 11) + 1023 - rowA + sft) >> 1;
    long long bd1 = ((((long long)(rowA + 8)) << 11) + 1015 - rowA + sft) >> 1;

    for (int jt = 0; jt < 16; jt++) {
        int buf = jt % 3;
        if (jt == 15) asm volatile("cp.async.wait_group 0;\n");
        else          asm volatile("cp.async.wait_group 1;\n");
        __syncthreads();

        // ---- prefetch BD band pairs (hidden behind the S MMAs below) ----
        int j0 = jt * 64;
        unsigned pb0[8], pb1[8];
#pragma unroll
        for (int nt = 0; nt < 8; nt++) {
            int jc = j0 + nt * 8 + 2 * lq;
            pb0[nt] = __ldg(bdz32 + bd0 + (jc >> 1));
            pb1[nt] = __ldg(bdz32 + bd1 + (jc >> 1));
        }

        // ---- S = Q1 @ K^T ----
        unsigned* cK = sK + buf * 2048;
        float S[8][4] = {};
#pragma unroll
        for (int s = 0; s < 4; s++) {
            unsigned a[4];
            a[0] = sQ[adru(rb, s * 8 + lq)];
            a[1] = sQ[adru(rb + 8, s * 8 + lq)];
            a[2] = sQ[adru(rb, s * 8 + 4 + lq)];
            a[3] = sQ[adru(rb + 8, s * 8 + 4 + lq)];
#pragma unroll
            for (int nt = 0; nt < 8; nt++) {
                int nn = nt * 8 + lr;
                unsigned bfx[2];
                bfx[0] = cK[adru(nn, s * 8 + lq)];
                bfx[1] = cK[adru(nn, s * 8 + 4 + lq)];
                MMA_BF16(S[nt], a, bfx);
            }
        }

        // ---- combine BD, scale, mask ----
#pragma unroll
        for (int nt = 0; nt < 8; nt++) {
            int jc = j0 + nt * 8 + 2 * lq;
            float2 f0 = __bfloat1622float2(*reinterpret_cast<__nv_bfloat162*>(&pb0[nt]));
            float2 f1 = __bfloat1622float2(*reinterpret_cast<__nv_bfloat162*>(&pb1[nt]));
            float s0 = (S[nt][0] + f0.x) * SCALE_F;
            float s1 = (S[nt][1] + f0.y) * SCALE_F;
            float s2 = (S[nt][2] + f1.x) * SCALE_F;
            float s3 = (S[nt][3] + f1.y) * SCALE_F;
            if (sMask[jc] != 0.f)     { s0 = -1e30f; s2 = -1e30f; }
            if (sMask[jc + 1] != 0.f) { s1 = -1e30f; s3 = -1e30f; }
            S[nt][0] = s0; S[nt][1] = s1; S[nt][2] = s2; S[nt][3] = s3;
        }

        // ---- online softmax ----
        float mxA = -3.4e38f, mxB = -3.4e38f;
#pragma unroll
        for (int nt = 0; nt < 8; nt++) {
            mxA = fmaxf(mxA, fmaxf(S[nt][0], S[nt][1]));
            mxB = fmaxf(mxB, fmaxf(S[nt][2], S[nt][3]));
        }
        mxA = fmaxf(mxA, __shfl_xor_sync(0xffffffffu, mxA, 1));
        mxA = fmaxf(mxA, __shfl_xor_sync(0xffffffffu, mxA, 2));
        mxB = fmaxf(mxB, __shfl_xor_sync(0xffffffffu, mxB, 1));
        mxB = fmaxf(mxB, __shfl_xor_sync(0xffffffffu, mxB, 2));
        float nmA = fmaxf(mA, mxA), nmB = fmaxf(mB, mxB);
        float scA = __expf(mA - nmA), scB = __expf(mB - nmB);
        mA = nmA; mB = nmB;
        float smA = 0.f, smB = 0.f;
#pragma unroll
        for (int nt = 0; nt < 8; nt++) {
            float p0 = __expf(S[nt][0] - nmA), p1 = __expf(S[nt][1] - nmA);
            float p2 = __expf(S[nt][2] - nmB), p3 = __expf(S[nt][3] - nmB);
            smA += p0 + p1; smB += p2 + p3;
            sP[adru(rb, nt * 4 + lq)] = packbf(p0, p1);
            sP[adru(rb + 8, nt * 4 + lq)] = packbf(p2, p3);
        }
        smA += __shfl_xor_sync(0xffffffffu, smA, 1);
        smA += __shfl_xor_sync(0xffffffffu, smA, 2);
        smB += __shfl_xor_sync(0xffffffffu, smB, 1);
        smB += __shfl_xor_sync(0xffffffffu, smB, 2);
        lA = lA * scA + smA;
        lB = lB * scB + smB;
#pragma unroll
        for (int nt = 0; nt < 8; nt++) {
            O[nt][0] *= scA; O[nt][1] *= scA;
            O[nt][2] *= scB; O[nt][3] *= scB;
        }
        __syncwarp();  // sP rows are warp-private

        // ---- O += P @ V ----
        unsigned* cV = sVt + buf * 2048;
#pragma unroll
        for (int s = 0; s < 4; s++) {
            unsigned a[4];
            a[0] = sP[adru(rb, s * 8 + lq)];
            a[1] = sP[adru(rb + 8, s * 8 + lq)];
            a[2] = sP[adru(rb, s * 8 + 4 + lq)];
            a[3] = sP[adru(rb + 8, s * 8 + 4 + lq)];
#pragma unroll
            for (int nt = 0; nt < 8; nt++) {
                int nn = nt * 8 + lr;
                unsigned bfx[2];
                bfx[0] = cV[adru(nn, s * 8 + lq)];
                bfx[1] = cV[adru(nn, s * 8 + 4 + lq)];
                MMA_BF16(O[nt], a, bfx);
            }
        }

        if (jt + 2 < 16) loadKV(jt + 2, (jt + 2) % 3);
    }

    // ---- finalize: normalize, pack bf16x2, store vec ----
    float iA = 1.0f / lA, iB = 1.0f / lB;
#pragma unroll
    for (int nt = 0; nt < 8; nt++) {
        int cp = (nh << 5) + nt * 4 + lq;  // pair column index
        vecu[(((long long)(rowA * 2 + b)) << 9) + cp] = packbf(O[nt][0] * iA, O[nt][1] * iA);
        vecu[(((long long)((rowA + 8) * 2 + b)) << 9) + cp] = packbf(O[nt][2] * iB, O[nt][3] * iB);
    }
}

// ---------------- residual + LayerNorm ----------------
__global__ void ln_k(const float* __restrict__ w, const float* __restrict__ xb,
                     const float* __restrict__ g, const float* __restrict__ bb,
                     float* __restrict__ out) {
    __shared__ float smr[16];
    int row = blockIdx.x, t = threadIdx.x;
    const float* wr = w + (long long)row * 1024;
    const float* xr = xb + (long long)row * 1024;
    float loc[4], s = 0.f, sq = 0.f;
#pragma unroll
    for (int e = 0; e < 4; e++) {
        float x = wr[e * 256 + t] + xr[e * 256 + t];
        loc[e] = x; s += x; sq += x * x;
    }
#pragma unroll
    for (int o = 16; o; o >>= 1) {
        s += __shfl_xor_sync(0xffffffffu, s, o);
        sq += __shfl_xor_sync(0xffffffffu, sq, o);
    }
    if ((t & 31) == 0) { smr[t >> 5] = s; smr[8 + (t >> 5)] = sq; }
    __syncthreads();
    s = smr[t & 7]; sq = smr[8 + (t & 7)];
#pragma unroll
    for (int o = 4; o; o >>= 1) {
        s += __shfl_xor_sync(0xffffffffu, s, o);
        sq += __shfl_xor_sync(0xffffffffu, sq, o);
    }
    float mu = s * (1.0f / 1024.0f);
    float var = sq * (1.0f / 1024.0f) - mu * mu;
    float rstd = rsqrtf(var + EPS_F);
#pragma unroll
    for (int e = 0; e < 4; e++) {
        int c = e * 256 + t;
        out[(long long)row * 1024 + c] = (loc[e] - mu) * rstd * g[c] + bb[c];
    }
}

// ---------------- launch ----------------
extern "C" void kernel_launch(void* const* d_in, const int* in_sizes, int n_in,
                              void* d_out, int out_size) {
    const float* w    = (const float*)d_in[0];
    const float* r    = (const float*)d_in[1];
    const float* rwb  = (const float*)d_in[2];
    const float* rrb  = (const float*)d_in[3];
    const unsigned char* mask = (const unsigned char*)d_in[4];
    const float* Wqkv = (const float*)d_in[5];
    const float* Wrfw = (const float*)d_in[6];
    const float* Wrbw = (const float*)d_in[7];
    const float* Wo   = (const float*)d_in[8];
    const float* lng  = (const float*)d_in[9];
    const float* lnb  = (const float*)d_in[10];
    float* out = (float*)d_out;

    unsigned *wu, *ru, *WqkvT, *WrfwT, *WrbwT, *WoT;
    unsigned *q1u, *q2u, *kku, *rku, *vvt, *vecu;
    __nv_bfloat16* bdh;
    float *vv, *xb;
    cudaGetSymbolAddress((void**)&wu, g_wu);
    cudaGetSymbolAddress((void**)&ru, g_ru);
    cudaGetSymbolAddress((void**)&WqkvT, g_WqkvT);
    cudaGetSymbolAddress((void**)&WrfwT, g_WrfwT);
    cudaGetSymbolAddress((void**)&WrbwT, g_WrbwT);
    cudaGetSymbolAddress((void**)&WoT, g_WoT);
    cudaGetSymbolAddress((void**)&q1u, g_q1u);
    cudaGetSymbolAddress((void**)&q2u, g_q2u);
    cudaGetSymbolAddress((void**)&kku, g_kku);
    cudaGetSymbolAddress((void**)&vv, g_vv);
    cudaGetSymbolAddress((void**)&vvt, g_vvt);
    cudaGetSymbolAddress((void**)&rku, g_rku);
    cudaGetSymbolAddress((void**)&bdh, g_bdh);
    cudaGetSymbolAddress((void**)&vecu, g_vecu);
    cudaGetSymbolAddress((void**)&xb, g_x);

    zero_u<<<2, 256>>>(rku + 2047 * 512);

    // pack inputs to bf16x2
    pack_k<<<4096, 256>>>(w, wu, 2048 * 512);
    pack_k<<<2048, 256>>>(r, ru, 1024 * 512);
    packT_k<<<dim3(48, 16), 256>>>(Wqkv, WqkvT, 3072);
    packT3_k<<<dim3(16, 16, 3), 256>>>(Wrfw, WrfwT, Wrbw, WrbwT, Wo, WoT);

    int bg_smem = 2 * 8192 * 4;  // 64 KB
    cudaFuncSetAttribute(bgemm_k<0>, cudaFuncAttributeMaxDynamicSharedMemorySize, bg_smem);
    cudaFuncSetAttribute(bgemm_k<2>, cudaFuncAttributeMaxDynamicSharedMemorySize, bg_smem);
    cudaFuncSetAttribute(bgemm_k<3>, cudaFuncAttributeMaxDynamicSharedMemorySize, bg_smem);

    // QKV GEMM (bf16) with fused head scatter
    bgemm_k<2><<<dim3(24, 16), 256, bg_smem>>>(wu, WqkvT, 512, 512, 512,
                                               nullptr, rwb, rrb, q1u, q2u, kku, vv);
    // merged r_fw (bx<8) + r_bw reversed (bx>=8) -> rku
    bgemm_k<3><<<dim3(16, 8), 256, bg_smem>>>(ru, WrfwT, 512, 512, 512,
                                              WrbwT, nullptr, nullptr,
                                              rku, rku + 2046 * 512, nullptr, nullptr);
    // V transpose -> bf16x2 [z][d][j/2]
    vt_k<<<dim3(8, 32), 256>>>(vv, vvt);
    // BD band (row-parity-shifted bf16)
    bd_k<<<dim3(9, 8, 32), 256>>>(q2u, rku, bdh);
    // fused AC + BD + mask + softmax + PV -> vec bf16x2
    int fl_smem = (4096 + 4096 + 3 * 2048 + 3 * 2048) * 4 + 1024 * 4;
    cudaFuncSetAttribute(flash_k, cudaFuncAttributeMaxDynamicSharedMemorySize, fl_smem);
    flash_k<<<dim3(8, 32), 256, fl_smem>>>(q1u, kku, vvt, bdh, mask, vecu);
    // attn_out = vec @ W_o (bf16)
    bgemm_k<0><<<dim3(8, 16), 256, bg_smem>>>(vecu, WoT, 512, 512, 512,
                                              nullptr, nullptr, nullptr,
                                              nullptr, nullptr, nullptr, xb);
    // residual + LN
    ln_k<<<2048, 256>>>(w, xb, lng, lnb, out);
}

// round 12
// speedup vs baseline: 1.1473x; 1.1473x over previous
#include <cuda_runtime.h>
#include <cuda_bf16.h>
#include <math.h>

#define SCALE_F 0.125f
#define EPS_F 1e-5f

// ---------------- scratch (device globals) ----------------
__device__ unsigned g_wu[2048 * 512];       // w packed bf16x2 [row][k/2]
__device__ unsigned g_ru[1024 * 512];       // r packed bf16x2
__device__ unsigned g_WqkvT[3072 * 512];    // W_qkv^T bf16x2 [n][k/2]
__device__ unsigned g_WrfwT[1024 * 512];    // W_r_fw^T bf16x2
__device__ unsigned g_WrbwT[1024 * 512];    // W_r_bw^T bf16x2
__device__ unsigned g_WoT[1024 * 512];      // W_o^T bf16x2
__device__ unsigned g_q1u[32 * 1024 * 32];  // q + r_w_bias, bf16x2 [z][i][32]
__device__ unsigned g_q2u[32 * 1024 * 32];  // q + r_r_bias, bf16x2
__device__ unsigned g_kku[32 * 1024 * 32];  // k heads, bf16x2
__device__ float    g_vv[32 * 1024 * 64];   // v heads fp32 [z][i][64]
__device__ unsigned g_vvt[32 * 64 * 512];   // v transposed bf16x2 [z][d][j/2]
__device__ unsigned g_rku[2048 * 512];      // r_k bf16x2 [jr][512] (row 2047 zeroed)
__device__ __nv_bfloat16 g_bdh[67108864];   // BD bf16 [z][1024][2048] (band only)
__device__ unsigned g_vecu[2048 * 512];     // attn vec bf16x2 [(i*2+b)][(n*64+d)/2]
__device__ float    g_x[2048 * 1024];       // vec @ W_o fp32

// ---------------- helpers ----------------
__device__ __forceinline__ void cp16(void* s, const void* g) {
    unsigned a = (unsigned)__cvta_generic_to_shared(s);
    asm volatile("cp.async.cg.shared.global [%0], [%1], 16;\n" ::"r"(a), "l"(g));
}
__device__ __forceinline__ unsigned packbf(float lo, float hi) {
    unsigned u;
    asm("cvt.rn.bf16x2.f32 %0, %1, %2;" : "=r"(u) : "f"(hi), "f"(lo));
    return u;
}
// bf16x2 rows of 32 u32 (=64 bf16), XOR swizzle
__device__ __forceinline__ int adru(int r, int c) {
    return r * 32 + (((c >> 2) ^ (r & 7)) << 2) + (c & 3);
}
#define MMA_BF16(c, a, b)                                                          \
    asm volatile(                                                                  \
        "mma.sync.aligned.m16n8k16.row.col.f32.bf16.bf16.f32 "                     \
        "{%0,%1,%2,%3},{%4,%5,%6,%7},{%8,%9},{%0,%1,%2,%3};"                       \
        : "+f"(c[0]), "+f"(c[1]), "+f"(c[2]), "+f"(c[3])                           \
        : "r"(a[0]), "r"(a[1]), "r"(a[2]), "r"(a[3]), "r"(b[0]), "r"(b[1]))

// ---------------- conversion kernels ----------------
__global__ __launch_bounds__(256) void pack_k(const float* __restrict__ in,
                                              unsigned* __restrict__ out, int n2) {
    int i = blockIdx.x * 256 + threadIdx.x;
    if (i < n2) {
        float2 v = ((const float2*)in)[i];
        out[i] = packbf(v.x, v.y);
    }
}
// fp32 [K][N] -> u32 [N][K/2] (transpose + pack). K=1024 (row stride 512 u32).
__device__ __forceinline__ void packT_body(const float* in, unsigned* out, int N) {
    __shared__ float ts[64][65];
    int t = threadIdx.x, n0 = blockIdx.x * 64, k0 = blockIdx.y * 64;
#pragma unroll
    for (int e = 0; e < 16; e++) {
        int idx = e * 256 + t, kk = idx >> 6, nn = idx & 63;
        ts[kk][nn] = in[(long long)(k0 + kk) * N + n0 + nn];
    }
    __syncthreads();
#pragma unroll
    for (int e = 0; e < 8; e++) {
        int idx = e * 256 + t, nn = idx >> 5, kp = idx & 31;
        out[(long long)(n0 + nn) * 512 + (k0 >> 1) + kp] =
            packbf(ts[2 * kp][nn], ts[2 * kp + 1][nn]);
    }
}
__global__ __launch_bounds__(256) void packT_k(const float* __restrict__ in,
                                               unsigned* __restrict__ out, int N) {
    packT_body(in, out, N);
}
// merged transpose-pack of three 1024x1024 weights (z selects)
__global__ __launch_bounds__(256) void packT3_k(
    const float* __restrict__ i0, unsigned* __restrict__ o0,
    const float* __restrict__ i1, unsigned* __restrict__ o1,
    const float* __restrict__ i2, unsigned* __restrict__ o2) {
    const float* in = (blockIdx.z == 0) ? i0 : (blockIdx.z == 1) ? i1 : i2;
    unsigned* out = (blockIdx.z == 0) ? o0 : (blockIdx.z == 1) ? o1 : o2;
    packT_body(in, out, 1024);
}
__global__ void zero_u(unsigned* p) { p[blockIdx.x * 256 + threadIdx.x] = 0u; }

// ---------------- bf16 GEMM 128x128, both operands u32 [rows][k/2] ----------------
// EPI 0: plain fp32 store to f4 (ldc=1024). EPI 2: QKV head scatter. EPI 3: rk.
template <int EPI>
__global__ __launch_bounds__(256, 2) void bgemm_k(
    const unsigned* __restrict__ A, const unsigned* __restrict__ B,
    int KU, int ldau, int ldbu,
    const unsigned* __restrict__ B2,
    const float* __restrict__ bias1, const float* __restrict__ bias2,
    unsigned* __restrict__ u1, unsigned* __restrict__ u2, unsigned* __restrict__ u3,
    float* __restrict__ f4) {
    extern __shared__ unsigned su[];
    int t = threadIdx.x, lane = t & 31, lq = lane & 3, lr = lane >> 2;
    int row0 = blockIdx.y * 128;
    int col0 = (EPI == 3) ? (blockIdx.x & 7) * 128 : blockIdx.x * 128;
    bool bw = (EPI == 3) && (blockIdx.x >= 8);
    if (bw) B = B2;
    int warp = t >> 5, wm = warp >> 1, wn = warp & 1;

    float acc[2][8][4] = {};

    auto load_tile = [&](int kt, int st) {
        unsigned* sA = su + st * 8192;
        unsigned* sB = sA + 4096;
        int k0 = kt * 32;
#pragma unroll
        for (int e = 0; e < 4; e++) {
            int c = e * 256 + t, r = c >> 3, c4 = c & 7;
            cp16(sA + r * 32 + ((c4 ^ (r & 7)) << 2),
                 A + (long long)(row0 + r) * ldau + k0 + c4 * 4);
            cp16(sB + r * 32 + ((c4 ^ (r & 7)) << 2),
                 B + (long long)(col0 + r) * ldbu + k0 + c4 * 4);
        }
        asm volatile("cp.async.commit_group;\n");
    };

    load_tile(0, 0);
    int KT = KU >> 5;
    for (int kt = 0; kt < KT; kt++) {
        int st = kt & 1;
        if (kt + 1 < KT) {
            load_tile(kt + 1, st ^ 1);
            asm volatile("cp.async.wait_group 1;\n");
        } else {
            asm volatile("cp.async.wait_group 0;\n");
        }
        __syncthreads();
        unsigned* sA = su + st * 8192;
        unsigned* sB = sA + 4096;
#pragma unroll
        for (int s = 0; s < 4; s++) {
            unsigned af[2][4], bf[8][2];
#pragma unroll
            for (int mt = 0; mt < 2; mt++) {
                int r = wm * 32 + mt * 16 + lr;
                af[mt][0] = sA[adru(r, s * 8 + lq)];
                af[mt][1] = sA[adru(r + 8, s * 8 + lq)];
                af[mt][2] = sA[adru(r, s * 8 + 4 + lq)];
                af[mt][3] = sA[adru(r + 8, s * 8 + 4 + lq)];
            }
#pragma unroll
            for (int nt = 0; nt < 8; nt++) {
                int nn = wn * 64 + nt * 8 + lr;
                bf[nt][0] = sB[adru(nn, s * 8 + lq)];
                bf[nt][1] = sB[adru(nn, s * 8 + 4 + lq)];
            }
#pragma unroll
            for (int mt = 0; mt < 2; mt++)
#pragma unroll
                for (int nt = 0; nt < 8; nt++) MMA_BF16(acc[mt][nt], af[mt], bf[nt]);
        }
        __syncthreads();
    }

#pragma unroll
    for (int mt = 0; mt < 2; mt++)
#pragma unroll
        for (int nt = 0; nt < 8; nt++) {
            int r0 = row0 + wm * 32 + mt * 16 + lr;
            int cb = col0 + wn * 64 + nt * 8 + 2 * lq;
#pragma unroll
            for (int pe = 0; pe < 2; pe++) {
                int rr = r0 + pe * 8;
                float v0 = acc[mt][nt][pe * 2], v1 = acc[mt][nt][pe * 2 + 1];
                if (EPI == 0) {
                    f4[(long long)rr * 1024 + cb] = v0;
                    f4[(long long)rr * 1024 + cb + 1] = v1;
                } else if (EPI == 3) {
                    if (bw) {
                        if (rr == 1023) continue;  // fw owns rk row 1023
                        u2[(long long)rr * (-512) + (cb >> 1)] = packbf(v0, v1);
                    } else {
                        u1[(long long)rr * 512 + (cb >> 1)] = packbf(v0, v1);
                    }
                } else {  // EPI == 2: QKV scatter
                    int i = rr >> 1, bb = rr & 1;
                    int sec = cb >> 10, c1 = cb & 1023, n = c1 >> 6, d = c1 & 63;
                    int z = bb * 16 + n;
                    if (sec == 0) {
                        long long idx = ((long long)z << 15) + (i << 5) + (d >> 1);
                        u1[idx] = packbf(v0 + bias1[c1], v1 + bias1[c1 + 1]);
                        u2[idx] = packbf(v0 + bias2[c1], v1 + bias2[c1 + 1]);
                    } else if (sec == 1) {
                        u3[((long long)z << 15) + (i << 5) + (d >> 1)] = packbf(v0, v1);
                    } else {
                        long long idx = ((long long)z << 16) + (i << 6) + d;
                        f4[idx] = v0; f4[idx + 1] = v1;
                    }
                }
            }
        }
}

// ---------------- V transpose: vv[z][j][d] fp32 -> vvt[z][d][j/2] bf16x2 ----------------
__global__ __launch_bounds__(256) void vt_k(const float* __restrict__ vv,
                                            unsigned* __restrict__ vvt) {
    __shared__ float ts[128][65];
    int t = threadIdx.x, z = blockIdx.y, j0 = blockIdx.x * 128;
    const float* Vz = vv + ((long long)z << 16);
#pragma unroll
    for (int e = 0; e < 8; e++) {
        int idx = e * 256 + t, r = idx >> 4, c4 = idx & 15;
        float4 v = *(const float4*)(Vz + (long long)(j0 + r) * 64 + c4 * 4);
        ts[r][c4 * 4] = v.x; ts[r][c4 * 4 + 1] = v.y;
        ts[r][c4 * 4 + 2] = v.z; ts[r][c4 * 4 + 3] = v.w;
    }
    __syncthreads();
#pragma unroll
    for (int e = 0; e < 16; e++) {
        int idx = e * 256 + t, d = idx >> 6, jp = idx & 63;
        vvt[((long long)z << 15) + (d << 9) + (j0 >> 1) + jp] =
            packbf(ts[jp * 2][d], ts[jp * 2 + 1][d]);
    }
}

// ---------------- bf16 BD band GEMM -> bf16 output (packed u32 stores) ----------------
__global__ __launch_bounds__(256, 2) void bd_k(
    const unsigned* __restrict__ q2, const unsigned* __restrict__ rk,
    unsigned* __restrict__ bdu) {
    __shared__ unsigned su[2 * 4096];
    unsigned* sA = su;
    unsigned* sB = su + 4096;
    int t = threadIdx.x, lane = t & 31, lq = lane & 3, lr = lane >> 2;
    int z = blockIdx.z;
    const unsigned* Az = q2 + ((long long)z << 15);
    const unsigned* Bz = rk + (long long)(z & 15) * 32;
    unsigned* Cz = bdu + ((long long)z << 20);
    int row0 = blockIdx.y * 128;
    int col0 = 896 - row0 + blockIdx.x * 128;
    int warp = t >> 5, wm = warp >> 1, wn = warp & 1;

#pragma unroll
    for (int e = 0; e < 4; e++) {
        int c = e * 256 + t, r = c >> 3, c4 = c & 7;
        cp16(sA + r * 32 + ((c4 ^ (r & 7)) << 2), Az + (long long)(row0 + r) * 32 + c4 * 4);
        cp16(sB + r * 32 + ((c4 ^ (r & 7)) << 2), Bz + (long long)(col0 + r) * 512 + c4 * 4);
    }
    asm volatile("cp.async.commit_group;\ncp.async.wait_group 0;\n");
    __syncthreads();

    float acc[2][8][4] = {};
#pragma unroll
    for (int s = 0; s < 4; s++) {
        unsigned af[2][4], bf[8][2];
#pragma unroll
        for (int mt = 0; mt < 2; mt++) {
            int r = wm * 32 + mt * 16 + lr;
            af[mt][0] = sA[adru(r, s * 8 + lq)];
            af[mt][1] = sA[adru(r + 8, s * 8 + lq)];
            af[mt][2] = sA[adru(r, s * 8 + 4 + lq)];
            af[mt][3] = sA[adru(r + 8, s * 8 + 4 + lq)];
        }
#pragma unroll
        for (int nt = 0; nt < 8; nt++) {
            int nn = wn * 64 + nt * 8 + lr;
            bf[nt][0] = sB[adru(nn, s * 8 + lq)];
            bf[nt][1] = sB[adru(nn, s * 8 + 4 + lq)];
        }
#pragma unroll
        for (int mt = 0; mt < 2; mt++)
#pragma unroll
            for (int nt = 0; nt < 8; nt++) MMA_BF16(acc[mt][nt], af[mt], bf[nt]);
    }

#pragma unroll
    for (int mt = 0; mt < 2; mt++)
#pragma unroll
        for (int nt = 0; nt < 8; nt++) {
            int r0 = row0 + wm * 32 + mt * 16 + lr;
            int cb = col0 + wn * 64 + nt * 8 + 2 * lq;
#pragma unroll
            for (int pe = 0; pe < 2; pe++) {
                int rr = r0 + pe * 8;
                Cz[((rr << 11) + cb) >> 1] = packbf(acc[mt][nt][pe * 2], acc[mt][nt][pe * 2 + 1]);
            }
        }
}

// ---------------- flash (bf16): S = Q1·K^T + BD_band, mask, online softmax, P·V ----------------
__global__ __launch_bounds__(256, 2) void flash_k(
    const unsigned* __restrict__ q1, const unsigned* __restrict__ kk,
    const unsigned* __restrict__ vvt, const __nv_bfloat16* __restrict__ bdh,
    const unsigned char* __restrict__ mask, unsigned* __restrict__ vecu) {
    extern __shared__ unsigned fsu[];
    unsigned* sQ = fsu;                   // 128 x 32 u32
    unsigned* sP = sQ + 4096;             // 128 x 32 u32
    unsigned* sK = sP + 4096;             // 3 x 64 x 32 u32
    unsigned* sVt = sK + 3 * 2048;        // 3 x 64 x 32 u32 (rows = d)
    float* sMask = (float*)(sVt + 3 * 2048);  // 1024 flags

    int t = threadIdx.x, lane = t & 31, warp = t >> 5;
    int lq = lane & 3, lr = lane >> 2;
    int i0 = blockIdx.x * 128, z = blockIdx.y, b = z >> 4, nh = z & 15;
    const unsigned* Qz = q1 + ((long long)z << 15);
    const unsigned* Kz = kk + ((long long)z << 15);
    const unsigned* Vtz = vvt + ((long long)z << 15);
    const __nv_bfloat16* bdz = bdh + ((long long)z << 21);

    for (int e = t; e < 1024; e += 256) sMask[e] = mask[e * 2 + b] ? 1.0f : 0.0f;

#pragma unroll
    for (int e = 0; e < 4; e++) {
        int c = e * 256 + t, r = c >> 3, c4 = c & 7;
        cp16(sQ + r * 32 + ((c4 ^ (r & 7)) << 2), Qz + (long long)(i0 + r) * 32 + c4 * 4);
    }
    auto loadKV = [&](int jt, int bufi) {
        unsigned* dK = sK + bufi * 2048;
        unsigned* dV = sVt + bufi * 2048;
        int j0 = jt * 64;
#pragma unroll
        for (int e = 0; e < 2; e++) {
            int c = e * 256 + t, r = c >> 3, c4 = c & 7;
            cp16(dK + r * 32 + ((c4 ^ (r & 7)) << 2), Kz + (long long)(j0 + r) * 32 + c4 * 4);
            cp16(dV + r * 32 + ((c4 ^ (r & 7)) << 2),
                 Vtz + ((long long)r << 9) + (j0 >> 1) + c4 * 4);
        }
        asm volatile("cp.async.commit_group;\n");
    };
    loadKV(0, 0);
    loadKV(1, 1);

    float mA = -3.4e38f, mB = -3.4e38f, lA = 0.f, lB = 0.f;
    float O[8][4] = {};
    int rb = warp * 16 + lr;
    int rowA = i0 + rb;

    for (int jt = 0; jt < 16; jt++) {
        int buf = jt % 3;
        if (jt == 15) asm volatile("cp.async.wait_group 0;\n");
        else          asm volatile("cp.async.wait_group 1;\n");
        __syncthreads();

        // ---- S = Q1 @ K^T ----
        unsigned* cK = sK + buf * 2048;
        float S[8][4] = {};
#pragma unroll
        for (int s = 0; s < 4; s++) {
            unsigned a[4];
            a[0] = sQ[adru(rb, s * 8 + lq)];
            a[1] = sQ[adru(rb + 8, s * 8 + lq)];
            a[2] = sQ[adru(rb, s * 8 + 4 + lq)];
            a[3] = sQ[adru(rb + 8, s * 8 + 4 + lq)];
#pragma unroll
            for (int nt = 0; nt < 8; nt++) {
                int nn = nt * 8 + lr;
                unsigned bfx[2];
                bfx[0] = cK[adru(nn, s * 8 + lq)];
                bfx[1] = cK[adru(nn, s * 8 + 4 + lq)];
                MMA_BF16(S[nt], a, bfx);
            }
        }

        // ---- add BD band (bf16 scalar loads), scale, mask ----
        int j0 = jt * 64;
#pragma unroll
        for (int nt = 0; nt < 8; nt++) {
            int jc = j0 + nt * 8 + 2 * lq;
            const __nv_bfloat16* b0 = bdz + (long long)rowA * 2048 + (1023 - rowA + jc);
            const __nv_bfloat16* b1 = bdz + (long long)(rowA + 8) * 2048 + (1015 - rowA + jc);
            float s0 = (S[nt][0] + __bfloat162float(__ldg(b0))) * SCALE_F;
            float s1 = (S[nt][1] + __bfloat162float(__ldg(b0 + 1))) * SCALE_F;
            float s2 = (S[nt][2] + __bfloat162float(__ldg(b1))) * SCALE_F;
            float s3 = (S[nt][3] + __bfloat162float(__ldg(b1 + 1))) * SCALE_F;
            if (sMask[jc] != 0.f)     { s0 = -1e30f; s2 = -1e30f; }
            if (sMask[jc + 1] != 0.f) { s1 = -1e30f; s3 = -1e30f; }
            S[nt][0] = s0; S[nt][1] = s1; S[nt][2] = s2; S[nt][3] = s3;
        }

        // ---- online softmax ----
        float mxA = -3.4e38f, mxB = -3.4e38f;
#pragma unroll
        for (int nt = 0; nt < 8; nt++) {
            mxA = fmaxf(mxA, fmaxf(S[nt][0], S[nt][1]));
            mxB = fmaxf(mxB, fmaxf(S[nt][2], S[nt][3]));
        }
        mxA = fmaxf(mxA, __shfl_xor_sync(0xffffffffu, mxA, 1));
        mxA = fmaxf(mxA, __shfl_xor_sync(0xffffffffu, mxA, 2));
        mxB = fmaxf(mxB, __shfl_xor_sync(0xffffffffu, mxB, 1));
        mxB = fmaxf(mxB, __shfl_xor_sync(0xffffffffu, mxB, 2));
        float nmA = fmaxf(mA, mxA), nmB = fmaxf(mB, mxB);
        float scA = __expf(mA - nmA), scB = __expf(mB - nmB);
        mA = nmA; mB = nmB;
        float smA = 0.f, smB = 0.f;
#pragma unroll
        for (int nt = 0; nt < 8; nt++) {
            float p0 = __expf(S[nt][0] - nmA), p1 = __expf(S[nt][1] - nmA);
            float p2 = __expf(S[nt][2] - nmB), p3 = __expf(S[nt][3] - nmB);
            smA += p0 + p1; smB += p2 + p3;
            sP[adru(rb, nt * 4 + lq)] = packbf(p0, p1);
            sP[adru(rb + 8, nt * 4 + lq)] = packbf(p2, p3);
        }
        smA += __shfl_xor_sync(0xffffffffu, smA, 1);
        smA += __shfl_xor_sync(0xffffffffu, smA, 2);
        smB += __shfl_xor_sync(0xffffffffu, smB, 1);
        smB += __shfl_xor_sync(0xffffffffu, smB, 2);
        lA = lA * scA + smA;
        lB = lB * scB + smB;
#pragma unroll
        for (int nt = 0; nt < 8; nt++) {
            O[nt][0] *= scA; O[nt][1] *= scA;
            O[nt][2] *= scB; O[nt][3] *= scB;
        }
        __syncwarp();  // sP rows are warp-private

        // ---- O += P @ V ----
        unsigned* cV = sVt + buf * 2048;
#pragma unroll
        for (int s = 0; s < 4; s++) {
            unsigned a[4];
            a[0] = sP[adru(rb, s * 8 + lq)];
            a[1] = sP[adru(rb + 8, s * 8 + lq)];
            a[2] = sP[adru(rb, s * 8 + 4 + lq)];
            a[3] = sP[adru(rb + 8, s * 8 + 4 + lq)];
#pragma unroll
            for (int nt = 0; nt < 8; nt++) {
                int nn = nt * 8 + lr;
                unsigned bfx[2];
                bfx[0] = cV[adru(nn, s * 8 + lq)];
                bfx[1] = cV[adru(nn, s * 8 + 4 + lq)];
                MMA_BF16(O[nt], a, bfx);
            }
        }

        if (jt + 2 < 16) loadKV(jt + 2, (jt + 2) % 3);
    }

    // ---- finalize: normalize, pack bf16x2, store vec ----
    float iA = 1.0f / lA, iB = 1.0f / lB;
#pragma unroll
    for (int nt = 0; nt < 8; nt++) {
        int cp = (nh << 5) + nt * 4 + lq;  // pair column index
        vecu[(((long long)(rowA * 2 + b)) << 9) + cp] = packbf(O[nt][0] * iA, O[nt][1] * iA);
        vecu[(((long long)((rowA + 8) * 2 + b)) << 9) + cp] = packbf(O[nt][2] * iB, O[nt][3] * iB);
    }
}

// ---------------- residual + LayerNorm ----------------
__global__ void ln_k(const float* __restrict__ w, const float* __restrict__ xb,
                     const float* __restrict__ g, const float* __restrict__ bb,
                     float* __restrict__ out) {
    __shared__ float smr[16];
    int row = blockIdx.x, t = threadIdx.x;
    const float* wr = w + (long long)row * 1024;
    const float* xr = xb + (long long)row * 1024;
    float loc[4], s = 0.f, sq = 0.f;
#pragma unroll
    for (int e = 0; e < 4; e++) {
        float x = wr[e * 256 + t] + xr[e * 256 + t];
        loc[e] = x; s += x; sq += x * x;
    }
#pragma unroll
    for (int o = 16; o; o >>= 1) {
        s += __shfl_xor_sync(0xffffffffu, s, o);
        sq += __shfl_xor_sync(0xffffffffu, sq, o);
    }
    if ((t & 31) == 0) { smr[t >> 5] = s; smr[8 + (t >> 5)] = sq; }
    __syncthreads();
    s = smr[t & 7]; sq = smr[8 + (t & 7)];
#pragma unroll
    for (int o = 4; o; o >>= 1) {
        s += __shfl_xor_sync(0xffffffffu, s, o);
        sq += __shfl_xor_sync(0xffffffffu, sq, o);
    }
    float mu = s * (1.0f / 1024.0f);
    float var = sq * (1.0f / 1024.0f) - mu * mu;
    float rstd = rsqrtf(var + EPS_F);
#pragma unroll
    for (int e = 0; e < 4; e++) {
        int c = e * 256 + t;
        out[(long long)row * 1024 + c] = (loc[e] - mu) * rstd * g[c] + bb[c];
    }
}

// ---------------- launch ----------------
extern "C" void kernel_launch(void* const* d_in, const int* in_sizes, int n_in,
                              void* d_out, int out_size) {
    const float* w    = (const float*)d_in[0];
    const float* r    = (const float*)d_in[1];
    const float* rwb  = (const float*)d_in[2];
    const float* rrb  = (const float*)d_in[3];
    const unsigned char* mask = (const unsigned char*)d_in[4];
    const float* Wqkv = (const float*)d_in[5];
    const float* Wrfw = (const float*)d_in[6];
    const float* Wrbw = (const float*)d_in[7];
    const float* Wo   = (const float*)d_in[8];
    const float* lng  = (const float*)d_in[9];
    const float* lnb  = (const float*)d_in[10];
    float* out = (float*)d_out;

    unsigned *wu, *ru, *WqkvT, *WrfwT, *WrbwT, *WoT;
    unsigned *q1u, *q2u, *kku, *rku, *vvt, *vecu;
    __nv_bfloat16* bdh;
    float *vv, *xb;
    cudaGetSymbolAddress((void**)&wu, g_wu);
    cudaGetSymbolAddress((void**)&ru, g_ru);
    cudaGetSymbolAddress((void**)&WqkvT, g_WqkvT);
    cudaGetSymbolAddress((void**)&WrfwT, g_WrfwT);
    cudaGetSymbolAddress((void**)&WrbwT, g_WrbwT);
    cudaGetSymbolAddress((void**)&WoT, g_WoT);
    cudaGetSymbolAddress((void**)&q1u, g_q1u);
    cudaGetSymbolAddress((void**)&q2u, g_q2u);
    cudaGetSymbolAddress((void**)&kku, g_kku);
    cudaGetSymbolAddress((void**)&vv, g_vv);
    cudaGetSymbolAddress((void**)&vvt, g_vvt);
    cudaGetSymbolAddress((void**)&rku, g_rku);
    cudaGetSymbolAddress((void**)&bdh, g_bdh);
    cudaGetSymbolAddress((void**)&vecu, g_vecu);
    cudaGetSymbolAddress((void**)&xb, g_x);

    zero_u<<<2, 256>>>(rku + 2047 * 512);

    // pack inputs to bf16x2
    pack_k<<<4096, 256>>>(w, wu, 2048 * 512);
    pack_k<<<2048, 256>>>(r, ru, 1024 * 512);
    packT_k<<<dim3(48, 16), 256>>>(Wqkv, WqkvT, 3072);
    packT3_k<<<dim3(16, 16, 3), 256>>>(Wrfw, WrfwT, Wrbw, WrbwT, Wo, WoT);

    int bg_smem = 2 * 8192 * 4;  // 64 KB
    cudaFuncSetAttribute(bgemm_k<0>, cudaFuncAttributeMaxDynamicSharedMemorySize, bg_smem);
    cudaFuncSetAttribute(bgemm_k<2>, cudaFuncAttributeMaxDynamicSharedMemorySize, bg_smem);
    cudaFuncSetAttribute(bgemm_k<3>, cudaFuncAttributeMaxDynamicSharedMemorySize, bg_smem);

    // QKV GEMM (bf16) with fused head scatter
    bgemm_k<2><<<dim3(24, 16), 256, bg_smem>>>(wu, WqkvT, 512, 512, 512,
                                               nullptr, rwb, rrb, q1u, q2u, kku, vv);
    // merged r_fw (bx<8) + r_bw reversed (bx>=8) -> rku
    bgemm_k<3><<<dim3(16, 8), 256, bg_smem>>>(ru, WrfwT, 512, 512, 512,
                                              WrbwT, nullptr, nullptr,
                                              rku, rku + 2046 * 512, nullptr, nullptr);
    // V transpose -> bf16x2 [z][d][j/2]
    vt_k<<<dim3(8, 32), 256>>>(vv, vvt);
    // BD band (packed u32 stores)
    bd_k<<<dim3(9, 8, 32), 256>>>(q2u, rku, (unsigned*)bdh);
    // fused AC + BD + mask + softmax + PV -> vec bf16x2
    int fl_smem = (4096 + 4096 + 3 * 2048 + 3 * 2048) * 4 + 1024 * 4;
    cudaFuncSetAttribute(flash_k, cudaFuncAttributeMaxDynamicSharedMemorySize, fl_smem);
    flash_k<<<dim3(8, 32), 256, fl_smem>>>(q1u, kku, vvt, bdh, mask, vecu);
    // attn_out = vec @ W_o (bf16)
    bgemm_k<0><<<dim3(8, 16), 256, bg_smem>>>(vecu, WoT, 512, 512, 512,
                                              nullptr, nullptr, nullptr,
                                              nullptr, nullptr, nullptr, xb);
    // residual + LN
    ln_k<<<2048, 256>>>(w, xb, lng, lnb, out);
}